// round 2
// baseline (speedup 1.0000x reference)
#include <cuda_runtime.h>
#include <stdint.h>

// Problem constants
#define BB 4
#define LL 10000
#define KK 16
#define II 256
#define OO 256
#define KTOT (KK * II)   // 4096

// Tiling
#define MT 64            // M tile = 16 l-values * 4 batches
#define NT 64            // N (=O) tile
#define KT 32            // K-chunk (never crosses a k boundary: 256/32=8)
#define LT 16            // l's per CTA
#define APAD 4           // keep As rows 16B-aligned for LDS.128

__global__ __launch_bounds__(256, 4)
void piconv_gemm_kernel(const float* __restrict__ x,
                        const int* __restrict__ idx,
                        const float* __restrict__ mask,
                        const float* __restrict__ bias,
                        float* __restrict__ out)
{
    // A stored transposed: As[kc][m]
    __shared__ float As[KT][MT + APAD];
    __shared__ float Bs[KT][NT];
    __shared__ int   sIdx[LT][KK];

    const int tid  = threadIdx.x;
    const int l0   = blockIdx.x * LT;   // 625 blocks
    const int n0   = blockIdx.y * NT;   // 4 blocks

    // Stage gather indices for this CTA's 16 l-values (int32!)
    {
        int li = tid >> 4;
        int k  = tid & 15;
        sIdx[li][k] = idx[(l0 + li) * KK + k];
    }
    __syncthreads();

    // Micro-tile coordinates: 16x16 thread grid, 4x4 outputs each
    const int tx = tid & 15;   // along N
    const int ty = tid >> 4;   // along M

    float acc[4][4];
#pragma unroll
    for (int i = 0; i < 4; i++)
#pragma unroll
        for (int j = 0; j < 4; j++) acc[i][j] = 0.f;

    // A-load mapping: 32 lanes along i (coalesced), 8 row-groups
    const int a_c  = tid & 31;        // i offset within K-chunk
    const int a_r0 = (tid >> 5) * 8;  // first of 8 rows this thread loads

    // B-load mapping: 16 float4 along N, 16 rows (x2)
    const int b_f = tid & 15;
    const int b_r = tid >> 4;

    for (int kt = 0; kt < KTOT / KT; kt++) {
        const int k     = kt >> 3;          // which expert mask
        const int ibase = (kt & 7) * KT;    // i offset within that mask

        // ---- Load A tile (gathered), store transposed ----
#pragma unroll
        for (int j = 0; j < 8; j++) {
            const int r    = a_r0 + j;
            const int li   = r >> 2;
            const int b    = r & 3;
            const int jrow = sIdx[li][k];
            As[a_c][r] = x[((size_t)(b * LL + jrow)) * II + ibase + a_c];
        }

        // ---- Load B tile (weights), vectorized ----
#pragma unroll
        for (int j = 0; j < 2; j++) {
            const int c = b_r + j * 16;
            const float4 w = *(const float4*)
                &mask[((size_t)(k * II + ibase + c)) * OO + n0 + b_f * 4];
            *(float4*)&Bs[c][b_f * 4] = w;
        }
        __syncthreads();

        // ---- FMA micro-kernel ----
#pragma unroll
        for (int kc = 0; kc < KT; kc++) {
            const float4 av = *(const float4*)&As[kc][ty * 4];
            const float4 bv = *(const float4*)&Bs[kc][tx * 4];

            acc[0][0] += av.x * bv.x; acc[0][1] += av.x * bv.y;
            acc[0][2] += av.x * bv.z; acc[0][3] += av.x * bv.w;
            acc[1][0] += av.y * bv.x; acc[1][1] += av.y * bv.y;
            acc[1][2] += av.y * bv.z; acc[1][3] += av.y * bv.w;
            acc[2][0] += av.z * bv.x; acc[2][1] += av.z * bv.y;
            acc[2][2] += av.z * bv.z; acc[2][3] += av.z * bv.w;
            acc[3][0] += av.w * bv.x; acc[3][1] += av.w * bv.y;
            acc[3][2] += av.w * bv.z; acc[3][3] += av.w * bv.w;
        }
        __syncthreads();
    }

    // ---- Epilogue: add bias, write out[b][l][o] ----
    const float4 bs = *(const float4*)&bias[n0 + tx * 4];
#pragma unroll
    for (int i = 0; i < 4; i++) {
        const int r  = ty * 4 + i;
        const int li = r >> 2;
        const int b  = r & 3;
        float4 v;
        v.x = acc[i][0] + bs.x;
        v.y = acc[i][1] + bs.y;
        v.z = acc[i][2] + bs.z;
        v.w = acc[i][3] + bs.w;
        *(float4*)&out[((size_t)b * LL + (l0 + li)) * OO + n0 + tx * 4] = v;
    }
}

extern "C" void kernel_launch(void* const* d_in, const int* in_sizes, int n_in,
                              void* d_out, int out_size)
{
    const float* x    = (const float*)d_in[0];   // (4, 10000, 256) fp32
    const int*   idx  = (const int*)d_in[1];     // (10000, 16) int32 (jax x64 off)
    const float* mask = (const float*)d_in[2];   // (16, 256, 256) fp32
    const float* bias = (const float*)d_in[3];   // (256,) fp32
    float*       out  = (float*)d_out;           // (4, 10000, 256) fp32

    (void)in_sizes; (void)n_in; (void)out_size;

    dim3 grid(LL / LT, OO / NT);   // 625 x 4
    dim3 block(256);
    piconv_gemm_kernel<<<grid, block>>>(x, idx, mask, bias, out);
}

// round 4
// speedup vs baseline: 6.4102x; 6.4102x over previous
#include <cuda_runtime.h>
#include <cuda_fp16.h>
#include <stdint.h>

// ---------------- problem constants ----------------
#define BB 4
#define LL 10000
#define KK 16
#define II 256
#define OO 256
#define MTOT (BB * LL)          // 40000
#define MTILES 313              // ceil(40000 / 128)

// ---------------- device scratch ----------------
__device__ __align__(16) __half g_xh[(size_t)BB * LL * II];     // x in fp16
__device__ __align__(16) __half g_maskT[(size_t)KK * OO * II];  // mask transposed: [k][o][i]

// ---------------- helpers ----------------
__device__ __forceinline__ uint32_t smem_to_u32(const void* p) {
    uint32_t a;
    asm("{ .reg .u64 t; cvta.to.shared.u64 t, %1; cvt.u32.u64 %0, t; }"
        : "=r"(a) : "l"(p));
    return a;
}
__device__ __forceinline__ void cp_async16(uint32_t dst, const void* src) {
    asm volatile("cp.async.cg.shared.global [%0], [%1], 16;" :: "r"(dst), "l"(src));
}
#define CP_COMMIT() asm volatile("cp.async.commit_group;" ::: "memory")
#define CP_WAIT1()  asm volatile("cp.async.wait_group 1;" ::: "memory")

__device__ __forceinline__ void ldmx4(uint32_t& r0, uint32_t& r1, uint32_t& r2, uint32_t& r3,
                                      uint32_t addr) {
    asm volatile("ldmatrix.sync.aligned.m8n8.x4.shared.b16 {%0,%1,%2,%3}, [%4];"
                 : "=r"(r0), "=r"(r1), "=r"(r2), "=r"(r3) : "r"(addr));
}
__device__ __forceinline__ void mma16816(float* c, const uint32_t* a, uint32_t b0, uint32_t b1) {
    asm volatile(
        "mma.sync.aligned.m16n8k16.row.col.f32.f16.f16.f32 "
        "{%0,%1,%2,%3}, {%4,%5,%6,%7}, {%8,%9}, {%0,%1,%2,%3};"
        : "+f"(c[0]), "+f"(c[1]), "+f"(c[2]), "+f"(c[3])
        : "r"(a[0]), "r"(a[1]), "r"(a[2]), "r"(a[3]), "r"(b0), "r"(b1));
}

// ---------------- prologue 1: x fp32 -> fp16 ----------------
__global__ void convert_x_kernel(const float* __restrict__ x) {
    int t = blockIdx.x * blockDim.x + threadIdx.x;   // 2,560,000 threads, 4 floats each
    float4 v = ((const float4*)x)[t];
    __half2* dst = ((__half2*)g_xh) + 2 * t;
    dst[0] = __floats2half2_rn(v.x, v.y);
    dst[1] = __floats2half2_rn(v.z, v.w);
}

// ---------------- prologue 2: mask[k][i][o] -> maskT[k][o][i] fp16 ----------------
__global__ void transpose_mask_kernel(const float* __restrict__ mask) {
    __shared__ float ts[32][33];
    int k  = blockIdx.z;
    int i0 = blockIdx.y * 32;
    int o0 = blockIdx.x * 32;
    int tx = threadIdx.x, ty = threadIdx.y;
    ts[ty][tx] = mask[((size_t)k * II + (i0 + ty)) * OO + o0 + tx];
    __syncthreads();
    g_maskT[((size_t)k * OO + (o0 + ty)) * II + i0 + tx] = __float2half(ts[tx][ty]);
}

// ---------------- main kernel ----------------
// Dynamic smem: [0,2048) gather indices (32 l * 16 k), then 3 stages of
// (A tile 128x128B | B tile 128x128B) = 32KB per stage.
#define SM_IDX   0
#define SM_STAGE 2048
#define STAGE_BYTES 32768
#define DYN_SMEM (SM_STAGE + 3 * STAGE_BYTES)   // 100352

// Issue one K-chunk (64 i-elems) of gathered A + B into stage buffer.
__device__ __forceinline__ void issue_chunk(int c, uint32_t stage, const int* sIdx,
                                            int n0, int tid) {
    const int kexp  = c >> 2;
    const int ibase = (c & 3) * 64;
    const uint32_t Ab = stage;
    const uint32_t Bb = stage + 16384;
#pragma unroll
    for (int j = 0; j < 4; j++) {
        int s   = tid + 256 * j;
        int row = s >> 3, seg = s & 7;
        int li  = row >> 2, b = row & 3;
        int jr  = sIdx[li * 16 + kexp];
        const __half* src = g_xh + ((size_t)(b * LL + jr)) * II + ibase + seg * 8;
        uint32_t off = (uint32_t)(row * 128 + seg * 16);
        cp_async16(Ab + (off ^ ((row & 7) << 4)), src);
    }
#pragma unroll
    for (int j = 0; j < 4; j++) {
        int s   = tid + 256 * j;
        int row = s >> 3, seg = s & 7;
        const __half* src = g_maskT + ((size_t)(kexp * OO + n0 + row)) * II + ibase + seg * 8;
        uint32_t off = (uint32_t)(row * 128 + seg * 16);
        cp_async16(Bb + (off ^ ((row & 7) << 4)), src);
    }
}

__global__ void __launch_bounds__(256, 2)
piconv_mma_kernel(const int* __restrict__ idx,
                  const float* __restrict__ bias,
                  float* __restrict__ out) {
    extern __shared__ char sm[];
    const uint32_t sb = smem_to_u32(sm);
    const int tid    = threadIdx.x;
    const int lane   = tid & 31;
    const int wid    = tid >> 5;
    const int warp_m = wid >> 1;           // 0..3  (32 rows each)
    const int warp_n = wid & 1;            // 0..1  (64 cols each)
    const int tile   = blockIdx.x;         // M tile (128 rows)
    const int n0     = blockIdx.y * 128;   // N tile
    const int l0     = tile * 32;

    // Stage gather indices (32 l-values x 16 k), clamped for the tail tile
    int* sIdx = (int*)(sm + SM_IDX);
    {
#pragma unroll
        for (int e = tid; e < 512; e += 256) {
            int li = e >> 4, kk = e & 15;
            int l = l0 + li;
            if (l > LL - 1) l = LL - 1;
            sIdx[e] = idx[l * KK + kk];
        }
    }
    __syncthreads();

    float acc[2][8][4];
#pragma unroll
    for (int a = 0; a < 2; a++)
#pragma unroll
        for (int n = 0; n < 8; n++)
#pragma unroll
            for (int q = 0; q < 4; q++) acc[a][n][q] = 0.f;

    // Pipeline prologue: chunks 0 and 1 in flight
    issue_chunk(0, sb + SM_STAGE + 0 * STAGE_BYTES, sIdx, n0, tid);
    CP_COMMIT();
    issue_chunk(1, sb + SM_STAGE + 1 * STAGE_BYTES, sIdx, n0, tid);
    CP_COMMIT();

    // Per-lane ldmatrix address invariants
    const int rA        = warp_m * 32 + (lane & 15);        // A row (am=0)
    const uint32_t aRow = (uint32_t)rA * 128u;
    const uint32_t aPh  = (uint32_t)((rA & 7) << 4);        // same for am=1 (+16 rows)
    const int colAh     = (lane >> 4) * 16;                 // k half (bytes)
    const int rBb       = warp_n * 64 + (lane & 7) + ((lane >> 4) << 3);
    const uint32_t bPh  = (uint32_t)((lane & 7) << 4);      // (rB&7) invariant of nb
    const int colBh     = ((lane >> 3) & 1) * 16;

    for (int c = 0; c < 64; c++) {
        CP_WAIT1();            // chunk c complete (c+1 may still be in flight)
        __syncthreads();       // all warps see chunk c; all done reading buf (c+2)%3

        if (c + 2 < 64)
            issue_chunk(c + 2, sb + SM_STAGE + ((c + 2) % 3) * STAGE_BYTES, sIdx, n0, tid);
        CP_COMMIT();

        const uint32_t Ab = sb + SM_STAGE + (c % 3) * STAGE_BYTES;
        const uint32_t Bb = Ab + 16384;

#pragma unroll
        for (int ks = 0; ks < 4; ks++) {
            uint32_t a0[4], a1[4];
            const uint32_t offA = (uint32_t)(ks * 32 + colAh) ^ aPh;
            ldmx4(a0[0], a0[1], a0[2], a0[3], Ab + aRow + offA);
            ldmx4(a1[0], a1[1], a1[2], a1[3], Ab + aRow + 2048 + offA);  // am=1: +16 rows

#pragma unroll
            for (int nb = 0; nb < 4; nb++) {
                const int rB = rBb + nb * 16;
                uint32_t b0, b1, b2, b3;
                const uint32_t offB = (uint32_t)(ks * 32 + colBh) ^ bPh;
                ldmx4(b0, b1, b2, b3, Bb + (uint32_t)rB * 128u + offB);
                mma16816(acc[0][nb * 2 + 0], a0, b0, b1);
                mma16816(acc[1][nb * 2 + 0], a1, b0, b1);
                mma16816(acc[0][nb * 2 + 1], a0, b2, b3);
                mma16816(acc[1][nb * 2 + 1], a1, b2, b3);
            }
        }
    }

    // ---- Epilogue: bias add + store (row m -> (b = m&3, l = m>>2)) ----
#pragma unroll
    for (int am = 0; am < 2; am++) {
#pragma unroll
        for (int nb = 0; nb < 8; nb++) {
            const int o = n0 + warp_n * 64 + nb * 8 + (lane & 3) * 2;
            const float2 bz = *(const float2*)&bias[o];
            const int m = tile * 128 + warp_m * 32 + am * 16 + (lane >> 2);
            if (m < MTOT) {
                float2 v;
                v.x = acc[am][nb][0] + bz.x;
                v.y = acc[am][nb][1] + bz.y;
                *(float2*)&out[((size_t)(m & 3) * LL + (m >> 2)) * OO + o] = v;
            }
            const int m2 = m + 8;
            if (m2 < MTOT) {
                float2 v;
                v.x = acc[am][nb][2] + bz.x;
                v.y = acc[am][nb][3] + bz.y;
                *(float2*)&out[((size_t)(m2 & 3) * LL + (m2 >> 2)) * OO + o] = v;
            }
        }
    }
}

// ---------------- launch ----------------
extern "C" void kernel_launch(void* const* d_in, const int* in_sizes, int n_in,
                              void* d_out, int out_size) {
    const float* x    = (const float*)d_in[0];   // (4, 10000, 256) fp32
    const int*   idx  = (const int*)d_in[1];     // (10000, 16) int32
    const float* mask = (const float*)d_in[2];   // (16, 256, 256) fp32
    const float* bias = (const float*)d_in[3];   // (256,) fp32
    float*       out  = (float*)d_out;           // (4, 10000, 256) fp32

    (void)in_sizes; (void)n_in; (void)out_size;

    static bool attr_set = false;
    if (!attr_set) {
        cudaFuncSetAttribute(piconv_mma_kernel,
                             cudaFuncAttributeMaxDynamicSharedMemorySize, DYN_SMEM);
        attr_set = true;
    }

    convert_x_kernel<<<(BB * LL * II / 4 + 255) / 256, 256>>>(x);
    transpose_mask_kernel<<<dim3(OO / 32, II / 32, KK), dim3(32, 32)>>>(mask);
    piconv_mma_kernel<<<dim3(MTILES, 2), 256, DYN_SMEM>>>(idx, bias, out);
}

// round 5
// speedup vs baseline: 7.7129x; 1.2032x over previous
#include <cuda_runtime.h>
#include <cuda_fp16.h>
#include <stdint.h>

// ---------------- problem constants ----------------
#define BB 4
#define LL 10000
#define KK 16
#define II 256
#define OO 256
#define MTOT (BB * LL)          // 40000
#define MTILES 313              // ceil(40000 / 128)

// ---------------- device scratch ----------------
__device__ __align__(16) __half g_xh[(size_t)BB * LL * II];     // x in fp16
__device__ __align__(16) __half g_maskT[(size_t)KK * OO * II];  // mask transposed: [k][o][i]

// ---------------- helpers ----------------
__device__ __forceinline__ uint32_t smem_to_u32(const void* p) {
    uint32_t a;
    asm("{ .reg .u64 t; cvta.to.shared.u64 t, %1; cvt.u32.u64 %0, t; }"
        : "=r"(a) : "l"(p));
    return a;
}
__device__ __forceinline__ void cp_async16(uint32_t dst, const void* src) {
    asm volatile("cp.async.cg.shared.global [%0], [%1], 16;" :: "r"(dst), "l"(src));
}
#define CP_COMMIT() asm volatile("cp.async.commit_group;" ::: "memory")
#define CP_WAIT1()  asm volatile("cp.async.wait_group 1;" ::: "memory")

__device__ __forceinline__ void ldmx4(uint32_t& r0, uint32_t& r1, uint32_t& r2, uint32_t& r3,
                                      uint32_t addr) {
    asm volatile("ldmatrix.sync.aligned.m8n8.x4.shared.b16 {%0,%1,%2,%3}, [%4];"
                 : "=r"(r0), "=r"(r1), "=r"(r2), "=r"(r3) : "r"(addr));
}
__device__ __forceinline__ void mma16816(float* c, const uint32_t* a, uint32_t b0, uint32_t b1) {
    asm volatile(
        "mma.sync.aligned.m16n8k16.row.col.f32.f16.f16.f32 "
        "{%0,%1,%2,%3}, {%4,%5,%6,%7}, {%8,%9}, {%0,%1,%2,%3};"
        : "+f"(c[0]), "+f"(c[1]), "+f"(c[2]), "+f"(c[3])
        : "r"(a[0]), "r"(a[1]), "r"(a[2]), "r"(a[3]), "r"(b0), "r"(b1));
}

// ---------------- merged prologue ----------------
// blocks [0, 2500):  x fp32 -> fp16 (1024 threads x 4 floats)
// blocks [2500, 3524): mask[k][i][o] -> maskT[k][o][i] fp16 (32x32 transpose tiles)
__global__ void __launch_bounds__(1024)
prologue_kernel(const float* __restrict__ x, const float* __restrict__ mask) {
    if (blockIdx.x < 2500) {
        int t = blockIdx.x * 1024 + threadIdx.x;
        float4 v = ((const float4*)x)[t];
        __half2* dst = ((__half2*)g_xh) + 2 * t;
        dst[0] = __floats2half2_rn(v.x, v.y);
        dst[1] = __floats2half2_rn(v.z, v.w);
    } else {
        __shared__ float ts[32][33];
        int bb  = blockIdx.x - 2500;         // 0..1023
        int k   = bb >> 6;                   // 16 experts
        int rem = bb & 63;
        int i0  = (rem >> 3) * 32;
        int o0  = (rem & 7) * 32;
        int tx  = threadIdx.x & 31;
        int ty  = threadIdx.x >> 5;
        ts[ty][tx] = mask[((size_t)k * II + (i0 + ty)) * OO + o0 + tx];
        __syncthreads();
        g_maskT[((size_t)k * OO + (o0 + ty)) * II + i0 + tx] = __float2half(ts[tx][ty]);
    }
}

// ---------------- main kernel ----------------
// CTA tile: 128 (M) x 256 (N = all of O).  8 warps: 4 (M) x 2 (N), warp tile 32x128.
// Dynamic smem: [0,2048) gather indices; 3 stages of (A 128x128B | B 256x128B) = 48KB.
#define SM_IDX   0
#define SM_STAGE 2048
#define STAGE_BYTES 49152
#define A_BYTES  16384
#define DYN_SMEM (SM_STAGE + 3 * STAGE_BYTES)   // 149504

__device__ __forceinline__ void issue_chunk(int c, uint32_t stage, const int* sIdx, int tid) {
    const int kexp  = c >> 2;
    const int ibase = (c & 3) * 64;
    const uint32_t Ab = stage;
    const uint32_t Bb = stage + A_BYTES;
    // A: 128 rows x 128B, gathered
#pragma unroll
    for (int j = 0; j < 4; j++) {
        int s   = tid + 256 * j;
        int row = s >> 3, seg = s & 7;
        int li  = row >> 2, b = row & 3;
        int jr  = sIdx[li * 16 + kexp];
        const __half* src = g_xh + ((size_t)(b * LL + jr)) * II + ibase + seg * 8;
        uint32_t off = (uint32_t)(row * 128 + seg * 16);
        cp_async16(Ab + (off ^ ((row & 7) << 4)), src);
    }
    // B: 256 rows (o) x 128B
#pragma unroll
    for (int j = 0; j < 8; j++) {
        int s   = tid + 256 * j;
        int row = s >> 3, seg = s & 7;
        const __half* src = g_maskT + ((size_t)(kexp * OO + row)) * II + ibase + seg * 8;
        uint32_t off = (uint32_t)(row * 128 + seg * 16);
        cp_async16(Bb + (off ^ ((row & 7) << 4)), src);
    }
}

__global__ void __launch_bounds__(256, 1)
piconv_mma_kernel(const int* __restrict__ idx,
                  const float* __restrict__ bias,
                  float* __restrict__ out) {
    extern __shared__ char sm[];
    const uint32_t sb = smem_to_u32(sm);
    const int tid    = threadIdx.x;
    const int lane   = tid & 31;
    const int wid    = tid >> 5;
    const int warp_m = wid >> 1;           // 0..3  (32 rows each)
    const int warp_n = wid & 1;            // 0..1  (128 cols each)
    const int tile   = blockIdx.x;         // M tile (128 rows)
    const int l0     = tile * 32;

    // Stage gather indices (32 l-values x 16 k), clamped for the tail tile
    int* sIdx = (int*)(sm + SM_IDX);
#pragma unroll
    for (int e = tid; e < 512; e += 256) {
        int li = e >> 4, kk = e & 15;
        int l = l0 + li;
        if (l > LL - 1) l = LL - 1;
        sIdx[e] = idx[l * KK + kk];
    }
    __syncthreads();

    float acc[2][16][4];
#pragma unroll
    for (int a = 0; a < 2; a++)
#pragma unroll
        for (int n = 0; n < 16; n++)
#pragma unroll
            for (int q = 0; q < 4; q++) acc[a][n][q] = 0.f;

    issue_chunk(0, sb + SM_STAGE + 0 * STAGE_BYTES, sIdx, tid);
    CP_COMMIT();
    issue_chunk(1, sb + SM_STAGE + 1 * STAGE_BYTES, sIdx, tid);
    CP_COMMIT();

    // Per-lane ldmatrix address invariants (verified in R3)
    const int rA        = warp_m * 32 + (lane & 15);
    const uint32_t aRow = (uint32_t)rA * 128u;
    const uint32_t aPh  = (uint32_t)((rA & 7) << 4);
    const int colAh     = (lane >> 4) * 16;
    const int rBb       = warp_n * 128 + (lane & 7) + ((lane >> 4) << 3);
    const uint32_t bPh  = (uint32_t)((lane & 7) << 4);
    const int colBh     = ((lane >> 3) & 1) * 16;

    for (int c = 0; c < 64; c++) {
        CP_WAIT1();
        __syncthreads();

        if (c + 2 < 64)
            issue_chunk(c + 2, sb + SM_STAGE + ((c + 2) % 3) * STAGE_BYTES, sIdx, tid);
        CP_COMMIT();

        const uint32_t Ab = sb + SM_STAGE + (c % 3) * STAGE_BYTES;
        const uint32_t Bb = Ab + A_BYTES;

#pragma unroll
        for (int ks = 0; ks < 4; ks++) {
            uint32_t a0[4], a1[4];
            const uint32_t offA = (uint32_t)(ks * 32 + colAh) ^ aPh;
            ldmx4(a0[0], a0[1], a0[2], a0[3], Ab + aRow + offA);
            ldmx4(a1[0], a1[1], a1[2], a1[3], Ab + aRow + 2048 + offA);  // +16 rows

            const uint32_t offB = (uint32_t)(ks * 32 + colBh) ^ bPh;
#pragma unroll
            for (int nb = 0; nb < 8; nb++) {
                const int rB = rBb + nb * 16;
                uint32_t b0, b1, b2, b3;
                ldmx4(b0, b1, b2, b3, Bb + (uint32_t)rB * 128u + offB);
                mma16816(acc[0][nb * 2 + 0], a0, b0, b1);
                mma16816(acc[1][nb * 2 + 0], a1, b0, b1);
                mma16816(acc[0][nb * 2 + 1], a0, b2, b3);
                mma16816(acc[1][nb * 2 + 1], a1, b2, b3);
            }
        }
    }

    // ---- Epilogue: bias add + store (row m -> b = m&3, l = m>>2) ----
#pragma unroll
    for (int am = 0; am < 2; am++) {
#pragma unroll
        for (int nn = 0; nn < 16; nn++) {
            const int o = warp_n * 128 + nn * 8 + (lane & 3) * 2;
            const float2 bz = *(const float2*)&bias[o];
            const int m = tile * 128 + warp_m * 32 + am * 16 + (lane >> 2);
            if (m < MTOT) {
                float2 v;
                v.x = acc[am][nn][0] + bz.x;
                v.y = acc[am][nn][1] + bz.y;
                *(float2*)&out[((size_t)(m & 3) * LL + (m >> 2)) * OO + o] = v;
            }
            const int m2 = m + 8;
            if (m2 < MTOT) {
                float2 v;
                v.x = acc[am][nn][2] + bz.x;
                v.y = acc[am][nn][3] + bz.y;
                *(float2*)&out[((size_t)(m2 & 3) * LL + (m2 >> 2)) * OO + o] = v;
            }
        }
    }
}

// ---------------- launch ----------------
extern "C" void kernel_launch(void* const* d_in, const int* in_sizes, int n_in,
                              void* d_out, int out_size) {
    const float* x    = (const float*)d_in[0];   // (4, 10000, 256) fp32
    const int*   idx  = (const int*)d_in[1];     // (10000, 16) int32
    const float* mask = (const float*)d_in[2];   // (16, 256, 256) fp32
    const float* bias = (const float*)d_in[3];   // (256,) fp32
    float*       out  = (float*)d_out;           // (4, 10000, 256) fp32

    (void)in_sizes; (void)n_in; (void)out_size;

    static bool attr_set = false;
    if (!attr_set) {
        cudaFuncSetAttribute(piconv_mma_kernel,
                             cudaFuncAttributeMaxDynamicSharedMemorySize, DYN_SMEM);
        attr_set = true;
    }

    prologue_kernel<<<3524, 1024>>>(x, mask);
    piconv_mma_kernel<<<MTILES, 256, DYN_SMEM>>>(idx, bias, out);
}

// round 6
// speedup vs baseline: 8.1377x; 1.0551x over previous
#include <cuda_runtime.h>
#include <cuda_fp16.h>
#include <stdint.h>

// ---------------- problem constants ----------------
#define BB 4
#define LL 10000
#define KK 16
#define II 256
#define OO 256
#define MTOT (BB * LL)          // 40000
#define MTILES 313              // ceil(40000 / 128)

// ---------------- device scratch ----------------
__device__ __align__(16) __half g_xh[(size_t)BB * LL * II];     // x in fp16
__device__ __align__(16) __half g_maskT[(size_t)KK * OO * II];  // mask transposed: [k][o][i]

// ---------------- helpers ----------------
__device__ __forceinline__ uint32_t smem_to_u32(const void* p) {
    uint32_t a;
    asm("{ .reg .u64 t; cvta.to.shared.u64 t, %1; cvt.u32.u64 %0, t; }"
        : "=r"(a) : "l"(p));
    return a;
}
__device__ __forceinline__ void cp_async16(uint32_t dst, const void* src) {
    asm volatile("cp.async.cg.shared.global [%0], [%1], 16;" :: "r"(dst), "l"(src));
}
#define CP_COMMIT() asm volatile("cp.async.commit_group;" ::: "memory")
#define CP_WAIT1()  asm volatile("cp.async.wait_group 1;" ::: "memory")

__device__ __forceinline__ void ldmx4(uint32_t& r0, uint32_t& r1, uint32_t& r2, uint32_t& r3,
                                      uint32_t addr) {
    asm volatile("ldmatrix.sync.aligned.m8n8.x4.shared.b16 {%0,%1,%2,%3}, [%4];"
                 : "=r"(r0), "=r"(r1), "=r"(r2), "=r"(r3) : "r"(addr));
}
__device__ __forceinline__ void mma16816(float* c, const uint32_t* a, uint32_t b0, uint32_t b1) {
    asm volatile(
        "mma.sync.aligned.m16n8k16.row.col.f32.f16.f16.f32 "
        "{%0,%1,%2,%3}, {%4,%5,%6,%7}, {%8,%9}, {%0,%1,%2,%3};"
        : "+f"(c[0]), "+f"(c[1]), "+f"(c[2]), "+f"(c[3])
        : "r"(a[0]), "r"(a[1]), "r"(a[2]), "r"(a[3]), "r"(b0), "r"(b1));
}

// ---------------- merged prologue ----------------
// blocks [0, 2500):  x fp32 -> fp16 (1024 threads x 4 floats)
// blocks [2500, 3524): mask[k][i][o] -> maskT[k][o][i] fp16 (32x32 transpose tiles)
__global__ void __launch_bounds__(1024)
prologue_kernel(const float* __restrict__ x, const float* __restrict__ mask) {
    if (blockIdx.x < 2500) {
        int t = blockIdx.x * 1024 + threadIdx.x;
        float4 v = ((const float4*)x)[t];
        __half2* dst = ((__half2*)g_xh) + 2 * t;
        dst[0] = __floats2half2_rn(v.x, v.y);
        dst[1] = __floats2half2_rn(v.z, v.w);
    } else {
        __shared__ float ts[32][33];
        int bb  = blockIdx.x - 2500;         // 0..1023
        int k   = bb >> 6;                   // 16 experts
        int rem = bb & 63;
        int i0  = (rem >> 3) * 32;
        int o0  = (rem & 7) * 32;
        int tx  = threadIdx.x & 31;
        int ty  = threadIdx.x >> 5;
        ts[ty][tx] = mask[((size_t)k * II + (i0 + ty)) * OO + o0 + tx];
        __syncthreads();
        g_maskT[((size_t)k * OO + (o0 + ty)) * II + i0 + tx] = __float2half(ts[tx][ty]);
    }
}

// ---------------- main kernel ----------------
// CTA tile: 128 (M) x 256 (N = all of O).  16 warps: 4 (M) x 4 (N), warp tile 32x64.
// Dynamic smem: [0,2048) gather indices; 3 stages of (A 128x128B | B 256x128B) = 48KB.
#define SM_IDX   0
#define SM_STAGE 2048
#define STAGE_BYTES 49152
#define A_BYTES  16384
#define DYN_SMEM (SM_STAGE + 3 * STAGE_BYTES)   // 149504
#define NTHREADS 512

__device__ __forceinline__ void issue_chunk(int c, uint32_t stage, const int* sIdx, int tid) {
    const int kexp  = c >> 2;
    const int ibase = (c & 3) * 64;
    const uint32_t Ab = stage;
    const uint32_t Bb = stage + A_BYTES;
    // A: 128 rows x 128B (1024 16B-loads), gathered
#pragma unroll
    for (int j = 0; j < 2; j++) {
        int s   = tid + NTHREADS * j;
        int row = s >> 3, seg = s & 7;
        int li  = row >> 2, b = row & 3;
        int jr  = sIdx[li * 16 + kexp];
        const __half* src = g_xh + ((size_t)(b * LL + jr)) * II + ibase + seg * 8;
        uint32_t off = (uint32_t)(row * 128 + seg * 16);
        cp_async16(Ab + (off ^ ((row & 7) << 4)), src);
    }
    // B: 256 rows (o) x 128B (2048 16B-loads)
#pragma unroll
    for (int j = 0; j < 4; j++) {
        int s   = tid + NTHREADS * j;
        int row = s >> 3, seg = s & 7;
        const __half* src = g_maskT + ((size_t)(kexp * OO + row)) * II + ibase + seg * 8;
        uint32_t off = (uint32_t)(row * 128 + seg * 16);
        cp_async16(Bb + (off ^ ((row & 7) << 4)), src);
    }
}

__global__ void __launch_bounds__(NTHREADS, 1)
piconv_mma_kernel(const int* __restrict__ idx,
                  const float* __restrict__ bias,
                  float* __restrict__ out) {
    extern __shared__ char sm[];
    const uint32_t sb = smem_to_u32(sm);
    const int tid    = threadIdx.x;
    const int lane   = tid & 31;
    const int wid    = tid >> 5;
    const int warp_m = wid >> 2;           // 0..3  (32 rows each)
    const int warp_n = wid & 3;            // 0..3  (64 cols each)
    const int tile   = blockIdx.x;         // M tile (128 rows)
    const int l0     = tile * 32;

    // Stage gather indices (32 l-values x 16 k), clamped for the tail tile
    int* sIdx = (int*)(sm + SM_IDX);
    if (tid < 512) {
        int li = tid >> 4, kk = tid & 15;
        int l = l0 + li;
        if (l > LL - 1) l = LL - 1;
        sIdx[tid] = idx[l * KK + kk];
    }
    __syncthreads();

    float acc[2][8][4];
#pragma unroll
    for (int a = 0; a < 2; a++)
#pragma unroll
        for (int n = 0; n < 8; n++)
#pragma unroll
            for (int q = 0; q < 4; q++) acc[a][n][q] = 0.f;

    issue_chunk(0, sb + SM_STAGE + 0 * STAGE_BYTES, sIdx, tid);
    CP_COMMIT();
    issue_chunk(1, sb + SM_STAGE + 1 * STAGE_BYTES, sIdx, tid);
    CP_COMMIT();

    // Per-lane ldmatrix address invariants
    const int rA        = warp_m * 32 + (lane & 15);
    const uint32_t aRow = (uint32_t)rA * 128u;
    const uint32_t aPh  = (uint32_t)((rA & 7) << 4);
    const int colAh     = (lane >> 4) * 16;
    const int rBb       = warp_n * 64 + (lane & 7) + ((lane >> 4) << 3);
    const uint32_t bPh  = (uint32_t)((lane & 7) << 4);
    const int colBh     = ((lane >> 3) & 1) * 16;

    for (int c = 0; c < 64; c++) {
        CP_WAIT1();
        __syncthreads();

        if (c + 2 < 64)
            issue_chunk(c + 2, sb + SM_STAGE + ((c + 2) % 3) * STAGE_BYTES, sIdx, tid);
        CP_COMMIT();

        const uint32_t Ab = sb + SM_STAGE + (c % 3) * STAGE_BYTES;
        const uint32_t Bb = Ab + A_BYTES;

#pragma unroll
        for (int ks = 0; ks < 4; ks++) {
            uint32_t a0[4], a1[4];
            const uint32_t offA = (uint32_t)(ks * 32 + colAh) ^ aPh;
            ldmx4(a0[0], a0[1], a0[2], a0[3], Ab + aRow + offA);
            ldmx4(a1[0], a1[1], a1[2], a1[3], Ab + aRow + 2048 + offA);  // +16 rows

            const uint32_t offB = (uint32_t)(ks * 32 + colBh) ^ bPh;
#pragma unroll
            for (int nb = 0; nb < 4; nb++) {
                const int rB = rBb + nb * 16;
                uint32_t b0, b1, b2, b3;
                ldmx4(b0, b1, b2, b3, Bb + (uint32_t)rB * 128u + offB);
                mma16816(acc[0][nb * 2 + 0], a0, b0, b1);
                mma16816(acc[1][nb * 2 + 0], a1, b0, b1);
                mma16816(acc[0][nb * 2 + 1], a0, b2, b3);
                mma16816(acc[1][nb * 2 + 1], a1, b2, b3);
            }
        }
    }

    // ---- Epilogue: bias add + store (row m -> b = m&3, l = m>>2) ----
    const bool tail = (tile == MTILES - 1);
#pragma unroll
    for (int am = 0; am < 2; am++) {
#pragma unroll
        for (int nn = 0; nn < 8; nn++) {
            const int o = warp_n * 64 + nn * 8 + (lane & 3) * 2;
            const float2 bz = *(const float2*)&bias[o];
            const int m = tile * 128 + warp_m * 32 + am * 16 + (lane >> 2);
            if (!tail || m < MTOT) {
                float2 v;
                v.x = acc[am][nn][0] + bz.x;
                v.y = acc[am][nn][1] + bz.y;
                *(float2*)&out[((size_t)(m & 3) * LL + (m >> 2)) * OO + o] = v;
            }
            const int m2 = m + 8;
            if (!tail || m2 < MTOT) {
                float2 v;
                v.x = acc[am][nn][2] + bz.x;
                v.y = acc[am][nn][3] + bz.y;
                *(float2*)&out[((size_t)(m2 & 3) * LL + (m2 >> 2)) * OO + o] = v;
            }
        }
    }
}

// ---------------- launch ----------------
extern "C" void kernel_launch(void* const* d_in, const int* in_sizes, int n_in,
                              void* d_out, int out_size) {
    const float* x    = (const float*)d_in[0];   // (4, 10000, 256) fp32
    const int*   idx  = (const int*)d_in[1];     // (10000, 16) int32
    const float* mask = (const float*)d_in[2];   // (16, 256, 256) fp32
    const float* bias = (const float*)d_in[3];   // (256,) fp32
    float*       out  = (float*)d_out;           // (4, 10000, 256) fp32

    (void)in_sizes; (void)n_in; (void)out_size;

    static bool attr_set = false;
    if (!attr_set) {
        cudaFuncSetAttribute(piconv_mma_kernel,
                             cudaFuncAttributeMaxDynamicSharedMemorySize, DYN_SMEM);
        attr_set = true;
    }

    prologue_kernel<<<3524, 1024>>>(x, mask);
    piconv_mma_kernel<<<MTILES, NTHREADS, DYN_SMEM>>>(idx, bias, out);
}

// round 7
// speedup vs baseline: 9.6825x; 1.1898x over previous
#include <cuda_runtime.h>
#include <cuda_fp16.h>
#include <stdint.h>

// ---------------- problem constants ----------------
#define BB 4
#define LL 10000
#define KK 16
#define II 256
#define OO 256
#define MTOT (BB * LL)          // 40000
#define MTILES 313              // ceil(40000 / 128)

// ---------------- device scratch ----------------
__device__ __align__(16) __half g_xh[(size_t)BB * LL * II];     // x in fp16
__device__ __align__(16) __half g_maskT[(size_t)KK * OO * II];  // mask transposed: [k][o][i]

// ---------------- helpers ----------------
__device__ __forceinline__ uint32_t smem_to_u32(const void* p) {
    uint32_t a;
    asm("{ .reg .u64 t; cvta.to.shared.u64 t, %1; cvt.u32.u64 %0, t; }"
        : "=r"(a) : "l"(p));
    return a;
}
__device__ __forceinline__ void cp_async16(uint32_t dst, const void* src) {
    asm volatile("cp.async.cg.shared.global [%0], [%1], 16;" :: "r"(dst), "l"(src));
}
#define CP_COMMIT() asm volatile("cp.async.commit_group;" ::: "memory")
#define CP_WAIT1()  asm volatile("cp.async.wait_group 1;" ::: "memory")

__device__ __forceinline__ void ldmx4(uint32_t& r0, uint32_t& r1, uint32_t& r2, uint32_t& r3,
                                      uint32_t addr) {
    asm volatile("ldmatrix.sync.aligned.m8n8.x4.shared.b16 {%0,%1,%2,%3}, [%4];"
                 : "=r"(r0), "=r"(r1), "=r"(r2), "=r"(r3) : "r"(addr));
}
__device__ __forceinline__ void mma16816(float* c, const uint32_t* a, uint32_t b0, uint32_t b1) {
    asm volatile(
        "mma.sync.aligned.m16n8k16.row.col.f32.f16.f16.f32 "
        "{%0,%1,%2,%3}, {%4,%5,%6,%7}, {%8,%9}, {%0,%1,%2,%3};"
        : "+f"(c[0]), "+f"(c[1]), "+f"(c[2]), "+f"(c[3])
        : "r"(a[0]), "r"(a[1]), "r"(a[2]), "r"(a[3]), "r"(b0), "r"(b1));
}

// ---------------- merged prologue ----------------
// blocks [0, 2500):  x fp32 -> fp16 (1024 threads x 4 floats)
// blocks [2500, 3524): mask[k][i][o] -> maskT[k][o][i] fp16 (32x32 transpose tiles)
__global__ void __launch_bounds__(1024)
prologue_kernel(const float* __restrict__ x, const float* __restrict__ mask) {
    if (blockIdx.x < 2500) {
        int t = blockIdx.x * 1024 + threadIdx.x;
        float4 v = ((const float4*)x)[t];
        __half2* dst = ((__half2*)g_xh) + 2 * t;
        dst[0] = __floats2half2_rn(v.x, v.y);
        dst[1] = __floats2half2_rn(v.z, v.w);
    } else {
        __shared__ float ts[32][33];
        int bb  = blockIdx.x - 2500;         // 0..1023
        int k   = bb >> 6;                   // 16 experts
        int rem = bb & 63;
        int i0  = (rem >> 3) * 32;
        int o0  = (rem & 7) * 32;
        int tx  = threadIdx.x & 31;
        int ty  = threadIdx.x >> 5;
        ts[ty][tx] = mask[((size_t)k * II + (i0 + ty)) * OO + o0 + tx];
        __syncthreads();
        g_maskT[((size_t)k * OO + (o0 + ty)) * II + i0 + tx] = __float2half(ts[tx][ty]);
    }
}

// ---------------- main kernel ----------------
// CTA tile: 128 (M) x 128 (N).  8 warps: 4 (M) x 2 (N), warp tile 32x64.
// Dynamic smem: [0,2048) gather indices; 3 stages of (A 128x128B | B 128x128B) = 32KB.
// 98KB/CTA -> 2 CTAs per SM with independent barrier phases.
#define SM_IDX   0
#define SM_STAGE 2048
#define STAGE_BYTES 32768
#define A_BYTES  16384
#define DYN_SMEM (SM_STAGE + 3 * STAGE_BYTES)   // 100352
#define NTHREADS 256

__device__ __forceinline__ void issue_chunk(int c, uint32_t stage, const int* sIdx,
                                            int n0, int tid) {
    const int kexp  = c >> 2;
    const int ibase = (c & 3) * 64;
    const uint32_t Ab = stage;
    const uint32_t Bb = stage + A_BYTES;
    // A: 128 rows x 128B (1024 16B-loads), gathered
#pragma unroll
    for (int j = 0; j < 4; j++) {
        int s   = tid + NTHREADS * j;
        int row = s >> 3, seg = s & 7;
        int li  = row >> 2, b = row & 3;
        int jr  = sIdx[li * 16 + kexp];
        const __half* src = g_xh + ((size_t)(b * LL + jr)) * II + ibase + seg * 8;
        uint32_t off = (uint32_t)(row * 128 + seg * 16);
        cp_async16(Ab + (off ^ ((row & 7) << 4)), src);
    }
    // B: 128 rows (o in [n0, n0+128)) x 128B
#pragma unroll
    for (int j = 0; j < 4; j++) {
        int s   = tid + NTHREADS * j;
        int row = s >> 3, seg = s & 7;
        const __half* src = g_maskT + ((size_t)(kexp * OO + n0 + row)) * II + ibase + seg * 8;
        uint32_t off = (uint32_t)(row * 128 + seg * 16);
        cp_async16(Bb + (off ^ ((row & 7) << 4)), src);
    }
}

__global__ void __launch_bounds__(NTHREADS, 2)
piconv_mma_kernel(const int* __restrict__ idx,
                  const float* __restrict__ bias,
                  float* __restrict__ out) {
    extern __shared__ char sm[];
    const uint32_t sb = smem_to_u32(sm);
    const int tid    = threadIdx.x;
    const int lane   = tid & 31;
    const int wid    = tid >> 5;
    const int warp_m = wid >> 1;           // 0..3  (32 rows each)
    const int warp_n = wid & 1;            // 0..1  (64 cols each)
    const int tile   = blockIdx.x;         // M tile (128 rows)
    const int n0     = blockIdx.y * 128;   // N tile
    const int l0     = tile * 32;

    // Stage gather indices (32 l-values x 16 k), clamped for the tail tile
    int* sIdx = (int*)(sm + SM_IDX);
#pragma unroll
    for (int e = tid; e < 512; e += NTHREADS) {
        int li = e >> 4, kk = e & 15;
        int l = l0 + li;
        if (l > LL - 1) l = LL - 1;
        sIdx[e] = idx[l * KK + kk];
    }
    __syncthreads();

    float acc[2][8][4];
#pragma unroll
    for (int a = 0; a < 2; a++)
#pragma unroll
        for (int n = 0; n < 8; n++)
#pragma unroll
            for (int q = 0; q < 4; q++) acc[a][n][q] = 0.f;

    issue_chunk(0, sb + SM_STAGE + 0 * STAGE_BYTES, sIdx, n0, tid);
    CP_COMMIT();
    issue_chunk(1, sb + SM_STAGE + 1 * STAGE_BYTES, sIdx, n0, tid);
    CP_COMMIT();

    // Per-lane ldmatrix address invariants
    const int rA        = warp_m * 32 + (lane & 15);
    const uint32_t aRow = (uint32_t)rA * 128u;
    const uint32_t aPh  = (uint32_t)((rA & 7) << 4);
    const int colAh     = (lane >> 4) * 16;
    const int rBb       = warp_n * 64 + (lane & 7) + ((lane >> 4) << 3);
    const uint32_t bPh  = (uint32_t)((lane & 7) << 4);
    const int colBh     = ((lane >> 3) & 1) * 16;

    for (int c = 0; c < 64; c++) {
        CP_WAIT1();
        __syncthreads();

        if (c + 2 < 64)
            issue_chunk(c + 2, sb + SM_STAGE + ((c + 2) % 3) * STAGE_BYTES, sIdx, n0, tid);
        CP_COMMIT();

        const uint32_t Ab = sb + SM_STAGE + (c % 3) * STAGE_BYTES;
        const uint32_t Bb = Ab + A_BYTES;

#pragma unroll
        for (int ks = 0; ks < 4; ks++) {
            uint32_t a0[4], a1[4];
            const uint32_t offA = (uint32_t)(ks * 32 + colAh) ^ aPh;
            ldmx4(a0[0], a0[1], a0[2], a0[3], Ab + aRow + offA);
            ldmx4(a1[0], a1[1], a1[2], a1[3], Ab + aRow + 2048 + offA);  // +16 rows

            const uint32_t offB = (uint32_t)(ks * 32 + colBh) ^ bPh;
#pragma unroll
            for (int nb = 0; nb < 4; nb++) {
                const int rB = rBb + nb * 16;
                uint32_t b0, b1, b2, b3;
                ldmx4(b0, b1, b2, b3, Bb + (uint32_t)rB * 128u + offB);
                mma16816(acc[0][nb * 2 + 0], a0, b0, b1);
                mma16816(acc[1][nb * 2 + 0], a1, b0, b1);
                mma16816(acc[0][nb * 2 + 1], a0, b2, b3);
                mma16816(acc[1][nb * 2 + 1], a1, b2, b3);
            }
        }
    }

    // ---- Epilogue: bias add + store (row m -> b = m&3, l = m>>2) ----
    const bool tail = (tile == MTILES - 1);
#pragma unroll
    for (int am = 0; am < 2; am++) {
#pragma unroll
        for (int nn = 0; nn < 8; nn++) {
            const int o = n0 + warp_n * 64 + nn * 8 + (lane & 3) * 2;
            const float2 bz = *(const float2*)&bias[o];
            const int m = tile * 128 + warp_m * 32 + am * 16 + (lane >> 2);
            if (!tail || m < MTOT) {
                float2 v;
                v.x = acc[am][nn][0] + bz.x;
                v.y = acc[am][nn][1] + bz.y;
                *(float2*)&out[((size_t)(m & 3) * LL + (m >> 2)) * OO + o] = v;
            }
            const int m2 = m + 8;
            if (!tail || m2 < MTOT) {
                float2 v;
                v.x = acc[am][nn][2] + bz.x;
                v.y = acc[am][nn][3] + bz.y;
                *(float2*)&out[((size_t)(m2 & 3) * LL + (m2 >> 2)) * OO + o] = v;
            }
        }
    }
}

// ---------------- launch ----------------
extern "C" void kernel_launch(void* const* d_in, const int* in_sizes, int n_in,
                              void* d_out, int out_size) {
    const float* x    = (const float*)d_in[0];   // (4, 10000, 256) fp32
    const int*   idx  = (const int*)d_in[1];     // (10000, 16) int32
    const float* mask = (const float*)d_in[2];   // (16, 256, 256) fp32
    const float* bias = (const float*)d_in[3];   // (256,) fp32
    float*       out  = (float*)d_out;           // (4, 10000, 256) fp32

    (void)in_sizes; (void)n_in; (void)out_size;

    static bool attr_set = false;
    if (!attr_set) {
        cudaFuncSetAttribute(piconv_mma_kernel,
                             cudaFuncAttributeMaxDynamicSharedMemorySize, DYN_SMEM);
        attr_set = true;
    }

    prologue_kernel<<<3524, 1024>>>(x, mask);
    piconv_mma_kernel<<<dim3(MTILES, 2), NTHREADS, DYN_SMEM>>>(idx, bias, out);
}

// round 8
// speedup vs baseline: 9.8477x; 1.0171x over previous
#include <cuda_runtime.h>
#include <cuda_fp16.h>
#include <stdint.h>

// ---------------- problem constants ----------------
#define BB 4
#define LL 10000
#define KK 16
#define II 256
#define OO 256
#define MTOT (BB * LL)          // 40000
#define MTILES 313              // ceil(40000 / 128)

// ---------------- device scratch ----------------
__device__ __align__(16) __half g_xh[(size_t)BB * LL * II];     // x in fp16
__device__ __align__(16) __half g_maskT[(size_t)KK * OO * II];  // mask transposed: [k][o][i]

// ---------------- helpers ----------------
__device__ __forceinline__ uint32_t smem_to_u32(const void* p) {
    uint32_t a;
    asm("{ .reg .u64 t; cvta.to.shared.u64 t, %1; cvt.u32.u64 %0, t; }"
        : "=r"(a) : "l"(p));
    return a;
}
__device__ __forceinline__ void cp_async16(uint32_t dst, const void* src) {
    asm volatile("cp.async.cg.shared.global [%0], [%1], 16;" :: "r"(dst), "l"(src));
}
#define CP_COMMIT() asm volatile("cp.async.commit_group;" ::: "memory")
#define CP_WAIT1()  asm volatile("cp.async.wait_group 1;" ::: "memory")

__device__ __forceinline__ void ldmx4(uint32_t& r0, uint32_t& r1, uint32_t& r2, uint32_t& r3,
                                      uint32_t addr) {
    asm volatile("ldmatrix.sync.aligned.m8n8.x4.shared.b16 {%0,%1,%2,%3}, [%4];"
                 : "=r"(r0), "=r"(r1), "=r"(r2), "=r"(r3) : "r"(addr));
}
__device__ __forceinline__ void mma16816(float* c, const uint32_t* a, uint32_t b0, uint32_t b1) {
    asm volatile(
        "mma.sync.aligned.m16n8k16.row.col.f32.f16.f16.f32 "
        "{%0,%1,%2,%3}, {%4,%5,%6,%7}, {%8,%9}, {%0,%1,%2,%3};"
        : "+f"(c[0]), "+f"(c[1]), "+f"(c[2]), "+f"(c[3])
        : "r"(a[0]), "r"(a[1]), "r"(a[2]), "r"(a[3]), "r"(b0), "r"(b1));
}

// ---------------- merged prologue ----------------
__global__ void __launch_bounds__(1024)
prologue_kernel(const float* __restrict__ x, const float* __restrict__ mask) {
    if (blockIdx.x < 2500) {
        int t = blockIdx.x * 1024 + threadIdx.x;
        float4 v = ((const float4*)x)[t];
        __half2* dst = ((__half2*)g_xh) + 2 * t;
        dst[0] = __floats2half2_rn(v.x, v.y);
        dst[1] = __floats2half2_rn(v.z, v.w);
    } else {
        __shared__ float ts[32][33];
        int bb  = blockIdx.x - 2500;         // 0..1023
        int k   = bb >> 6;                   // 16 experts
        int rem = bb & 63;
        int i0  = (rem >> 3) * 32;
        int o0  = (rem & 7) * 32;
        int tx  = threadIdx.x & 31;
        int ty  = threadIdx.x >> 5;
        ts[ty][tx] = mask[((size_t)k * II + (i0 + ty)) * OO + o0 + tx];
        __syncthreads();
        g_maskT[((size_t)k * OO + (o0 + ty)) * II + i0 + tx] = __float2half(ts[tx][ty]);
    }
}

// ---------------- main kernel ----------------
// CTA tile: 128 (M) x 128 (N). 4 warps: 2 (M) x 2 (N), warp tile 64x64.
// Dynamic smem: [0,2048) gather indices; 3 stages of (A 128x128B | B 128x128B) = 32KB.
// 98KB/CTA -> 2 CTAs/SM (independent barrier phases), full 255-reg budget per thread.
#define SM_IDX   0
#define SM_STAGE 2048
#define STAGE_BYTES 32768
#define A_BYTES  16384
#define DYN_SMEM (SM_STAGE + 3 * STAGE_BYTES)   // 100352
#define NTHREADS 128

__device__ __forceinline__ void issue_chunk(int c, uint32_t stage, const int* sIdx,
                                            int n0, int tid) {
    const int kexp  = c >> 2;
    const int ibase = (c & 3) * 64;
    const uint32_t Ab = stage;
    const uint32_t Bb = stage + A_BYTES;
    // A: 128 rows x 128B (1024 16B-loads), gathered
#pragma unroll
    for (int j = 0; j < 8; j++) {
        int s   = tid + NTHREADS * j;
        int row = s >> 3, seg = s & 7;
        int li  = row >> 2, b = row & 3;
        int jr  = sIdx[li * 16 + kexp];
        const __half* src = g_xh + ((size_t)(b * LL + jr)) * II + ibase + seg * 8;
        uint32_t off = (uint32_t)(row * 128 + seg * 16);
        cp_async16(Ab + (off ^ ((row & 7) << 4)), src);
    }
    // B: 128 rows (o in [n0, n0+128)) x 128B
#pragma unroll
    for (int j = 0; j < 8; j++) {
        int s   = tid + NTHREADS * j;
        int row = s >> 3, seg = s & 7;
        const __half* src = g_maskT + ((size_t)(kexp * OO + n0 + row)) * II + ibase + seg * 8;
        uint32_t off = (uint32_t)(row * 128 + seg * 16);
        cp_async16(Bb + (off ^ ((row & 7) << 4)), src);
    }
}

__global__ void __launch_bounds__(NTHREADS, 2)
piconv_mma_kernel(const int* __restrict__ idx,
                  const float* __restrict__ bias,
                  float* __restrict__ out) {
    extern __shared__ char sm[];
    const uint32_t sb = smem_to_u32(sm);
    const int tid    = threadIdx.x;
    const int lane   = tid & 31;
    const int wid    = tid >> 5;
    const int warp_m = wid >> 1;           // 0..1  (64 rows each)
    const int warp_n = wid & 1;            // 0..1  (64 cols each)
    const int tile   = blockIdx.x;         // M tile (128 rows)
    const int n0     = blockIdx.y * 128;   // N tile
    const int l0     = tile * 32;

    // Stage gather indices (32 l-values x 16 k), clamped for the tail tile
    int* sIdx = (int*)(sm + SM_IDX);
#pragma unroll
    for (int e = tid; e < 512; e += NTHREADS) {
        int li = e >> 4, kk = e & 15;
        int l = l0 + li;
        if (l > LL - 1) l = LL - 1;
        sIdx[e] = idx[l * KK + kk];
    }
    __syncthreads();

    // 64x64 warp tile: acc[am 0..3][nn 0..7][4] = 128 regs
    float acc[4][8][4];
#pragma unroll
    for (int a = 0; a < 4; a++)
#pragma unroll
        for (int n = 0; n < 8; n++)
#pragma unroll
            for (int q = 0; q < 4; q++) acc[a][n][q] = 0.f;

    issue_chunk(0, sb + SM_STAGE + 0 * STAGE_BYTES, sIdx, n0, tid);
    CP_COMMIT();
    issue_chunk(1, sb + SM_STAGE + 1 * STAGE_BYTES, sIdx, n0, tid);
    CP_COMMIT();

    // Per-lane ldmatrix address invariants
    const int rA        = warp_m * 64 + (lane & 15);      // am adds +16 rows (row&7 invariant)
    const uint32_t aRow = (uint32_t)rA * 128u;
    const uint32_t aPh  = (uint32_t)((rA & 7) << 4);
    const int colAh     = (lane >> 4) * 16;
    const int rBb       = warp_n * 64 + (lane & 7) + ((lane >> 4) << 3);  // nb adds +16 rows
    const uint32_t bPh  = (uint32_t)((lane & 7) << 4);
    const int colBh     = ((lane >> 3) & 1) * 16;

    for (int c = 0; c < 64; c++) {
        CP_WAIT1();
        __syncthreads();

        if (c + 2 < 64)
            issue_chunk(c + 2, sb + SM_STAGE + ((c + 2) % 3) * STAGE_BYTES, sIdx, n0, tid);
        CP_COMMIT();

        const uint32_t Ab = sb + SM_STAGE + (c % 3) * STAGE_BYTES;
        const uint32_t Bb = Ab + A_BYTES;

#pragma unroll
        for (int ks = 0; ks < 4; ks++) {
            uint32_t a[4][4];
            const uint32_t offA = (uint32_t)(ks * 32 + colAh) ^ aPh;
#pragma unroll
            for (int am = 0; am < 4; am++)
                ldmx4(a[am][0], a[am][1], a[am][2], a[am][3],
                      Ab + aRow + (uint32_t)am * 2048u + offA);

            const uint32_t offB = (uint32_t)(ks * 32 + colBh) ^ bPh;
            uint32_t b[4][4];
#pragma unroll
            for (int nb = 0; nb < 4; nb++) {
                const int rB = rBb + nb * 16;
                ldmx4(b[nb][0], b[nb][1], b[nb][2], b[nb][3],
                      Bb + (uint32_t)rB * 128u + offB);
            }
#pragma unroll
            for (int am = 0; am < 4; am++) {
#pragma unroll
                for (int nb = 0; nb < 4; nb++) {
                    mma16816(acc[am][nb * 2 + 0], a[am], b[nb][0], b[nb][1]);
                    mma16816(acc[am][nb * 2 + 1], a[am], b[nb][2], b[nb][3]);
                }
            }
        }
    }

    // ---- Epilogue: bias add + store (row m -> b = m&3, l = m>>2) ----
    const bool tail = (tile == MTILES - 1);
#pragma unroll
    for (int am = 0; am < 4; am++) {
#pragma unroll
        for (int nn = 0; nn < 8; nn++) {
            const int o = n0 + warp_n * 64 + nn * 8 + (lane & 3) * 2;
            const float2 bz = *(const float2*)&bias[o];
            const int m = tile * 128 + warp_m * 64 + am * 16 + (lane >> 2);
            if (!tail || m < MTOT) {
                float2 v;
                v.x = acc[am][nn][0] + bz.x;
                v.y = acc[am][nn][1] + bz.y;
                *(float2*)&out[((size_t)(m & 3) * LL + (m >> 2)) * OO + o] = v;
            }
            const int m2 = m + 8;
            if (!tail || m2 < MTOT) {
                float2 v;
                v.x = acc[am][nn][2] + bz.x;
                v.y = acc[am][nn][3] + bz.y;
                *(float2*)&out[((size_t)(m2 & 3) * LL + (m2 >> 2)) * OO + o] = v;
            }
        }
    }
}

// ---------------- launch ----------------
extern "C" void kernel_launch(void* const* d_in, const int* in_sizes, int n_in,
                              void* d_out, int out_size) {
    const float* x    = (const float*)d_in[0];   // (4, 10000, 256) fp32
    const int*   idx  = (const int*)d_in[1];     // (10000, 16) int32
    const float* mask = (const float*)d_in[2];   // (16, 256, 256) fp32
    const float* bias = (const float*)d_in[3];   // (256,) fp32
    float*       out  = (float*)d_out;           // (4, 10000, 256) fp32

    (void)in_sizes; (void)n_in; (void)out_size;

    static bool attr_set = false;
    if (!attr_set) {
        cudaFuncSetAttribute(piconv_mma_kernel,
                             cudaFuncAttributeMaxDynamicSharedMemorySize, DYN_SMEM);
        attr_set = true;
    }

    prologue_kernel<<<3524, 1024>>>(x, mask);
    piconv_mma_kernel<<<dim3(MTILES, 2), NTHREADS, DYN_SMEM>>>(idx, bias, out);
}

// round 9
// speedup vs baseline: 10.3574x; 1.0518x over previous
#include <cuda_runtime.h>
#include <cuda_fp16.h>
#include <stdint.h>

// ---------------- problem constants ----------------
#define BB 4
#define LL 10000
#define KK 16
#define II 256
#define OO 256
#define MTOT (BB * LL)          // 40000
#define MTILES 313              // ceil(40000 / 128)

// ---------------- device scratch ----------------
__device__ __align__(16) __half g_xh[(size_t)BB * LL * II];     // x in fp16
__device__ __align__(16) __half g_maskT[(size_t)KK * OO * II];  // mask transposed: [k][o][i]

// ---------------- helpers ----------------
__device__ __forceinline__ uint32_t smem_to_u32(const void* p) {
    uint32_t a;
    asm("{ .reg .u64 t; cvta.to.shared.u64 t, %1; cvt.u32.u64 %0, t; }"
        : "=r"(a) : "l"(p));
    return a;
}
__device__ __forceinline__ void cp_async16(uint32_t dst, const void* src) {
    asm volatile("cp.async.cg.shared.global [%0], [%1], 16;" :: "r"(dst), "l"(src));
}
#define CP_COMMIT() asm volatile("cp.async.commit_group;" ::: "memory")
#define CP_WAIT1()  asm volatile("cp.async.wait_group 1;" ::: "memory")

__device__ __forceinline__ void ldmx4(uint32_t& r0, uint32_t& r1, uint32_t& r2, uint32_t& r3,
                                      uint32_t addr) {
    asm volatile("ldmatrix.sync.aligned.m8n8.x4.shared.b16 {%0,%1,%2,%3}, [%4];"
                 : "=r"(r0), "=r"(r1), "=r"(r2), "=r"(r3) : "r"(addr));
}
__device__ __forceinline__ void mma16816(float* c, const uint32_t* a, uint32_t b0, uint32_t b1) {
    asm volatile(
        "mma.sync.aligned.m16n8k16.row.col.f32.f16.f16.f32 "
        "{%0,%1,%2,%3}, {%4,%5,%6,%7}, {%8,%9}, {%0,%1,%2,%3};"
        : "+f"(c[0]), "+f"(c[1]), "+f"(c[2]), "+f"(c[3])
        : "r"(a[0]), "r"(a[1]), "r"(a[2]), "r"(a[3]), "r"(b0), "r"(b1));
}

// ---------------- merged prologue ----------------
__global__ void __launch_bounds__(1024)
prologue_kernel(const float* __restrict__ x, const float* __restrict__ mask) {
    if (blockIdx.x < 2500) {
        int t = blockIdx.x * 1024 + threadIdx.x;
        float4 v = ((const float4*)x)[t];
        __half2* dst = ((__half2*)g_xh) + 2 * t;
        dst[0] = __floats2half2_rn(v.x, v.y);
        dst[1] = __floats2half2_rn(v.z, v.w);
    } else {
        __shared__ float ts[32][33];
        int bb  = blockIdx.x - 2500;         // 0..1023
        int k   = bb >> 6;                   // 16 experts
        int rem = bb & 63;
        int i0  = (rem >> 3) * 32;
        int o0  = (rem & 7) * 32;
        int tx  = threadIdx.x & 31;
        int ty  = threadIdx.x >> 5;
        ts[ty][tx] = mask[((size_t)k * II + (i0 + ty)) * OO + o0 + tx];
        __syncthreads();
        g_maskT[((size_t)k * OO + (o0 + ty)) * II + i0 + tx] = __float2half(ts[tx][ty]);
    }
}

// ---------------- main kernel ----------------
// CTA tile: 128 (M) x 64 (N). 4 warps: 2 (M) x 2 (N), warp tile 64x32.
// Dynamic smem: [0,2048) gather indices; 3 stages of (A 128x128B | B 64x128B) = 24KB.
// 74KB/CTA -> 3 CTAs/SM (3 independent barrier phases per SMSP; waves 2.82/3 = 94% util).
#define SM_IDX   0
#define SM_STAGE 2048
#define STAGE_BYTES 24576
#define A_BYTES  16384
#define DYN_SMEM (SM_STAGE + 3 * STAGE_BYTES)   // 75776
#define NTHREADS 128

__device__ __forceinline__ void issue_chunk(int c, uint32_t stage, const int* sIdx,
                                            int n0, int tid) {
    const int kexp  = c >> 2;
    const int ibase = (c & 3) * 64;
    const uint32_t Ab = stage;
    const uint32_t Bb = stage + A_BYTES;
    // A: 128 rows x 128B (1024 16B-loads), gathered
#pragma unroll
    for (int j = 0; j < 8; j++) {
        int s   = tid + NTHREADS * j;
        int row = s >> 3, seg = s & 7;
        int li  = row >> 2, b = row & 3;
        int jr  = sIdx[li * 16 + kexp];
        const __half* src = g_xh + ((size_t)(b * LL + jr)) * II + ibase + seg * 8;
        uint32_t off = (uint32_t)(row * 128 + seg * 16);
        cp_async16(Ab + (off ^ ((row & 7) << 4)), src);
    }
    // B: 64 rows (o in [n0, n0+64)) x 128B (512 16B-loads)
#pragma unroll
    for (int j = 0; j < 4; j++) {
        int s   = tid + NTHREADS * j;
        int row = s >> 3, seg = s & 7;
        const __half* src = g_maskT + ((size_t)(kexp * OO + n0 + row)) * II + ibase + seg * 8;
        uint32_t off = (uint32_t)(row * 128 + seg * 16);
        cp_async16(Bb + (off ^ ((row & 7) << 4)), src);
    }
}

__global__ void __launch_bounds__(NTHREADS, 3)
piconv_mma_kernel(const int* __restrict__ idx,
                  const float* __restrict__ bias,
                  float* __restrict__ out) {
    extern __shared__ char sm[];
    const uint32_t sb = smem_to_u32(sm);
    const int tid    = threadIdx.x;
    const int lane   = tid & 31;
    const int wid    = tid >> 5;
    const int warp_m = wid >> 1;           // 0..1  (64 rows each)
    const int warp_n = wid & 1;            // 0..1  (32 cols each)
    const int tile   = blockIdx.x;         // M tile (128 rows)
    const int n0     = blockIdx.y * 64;    // N tile
    const int l0     = tile * 32;

    // Stage gather indices (32 l-values x 16 k), clamped for the tail tile
    int* sIdx = (int*)(sm + SM_IDX);
#pragma unroll
    for (int e = tid; e < 512; e += NTHREADS) {
        int li = e >> 4, kk = e & 15;
        int l = l0 + li;
        if (l > LL - 1) l = LL - 1;
        sIdx[e] = idx[l * KK + kk];
    }
    __syncthreads();

    // 64x32 warp tile: acc[am 0..3][nn 0..3][4] = 64 regs
    float acc[4][4][4];
#pragma unroll
    for (int a = 0; a < 4; a++)
#pragma unroll
        for (int n = 0; n < 4; n++)
#pragma unroll
            for (int q = 0; q < 4; q++) acc[a][n][q] = 0.f;

    issue_chunk(0, sb + SM_STAGE + 0 * STAGE_BYTES, sIdx, n0, tid);
    CP_COMMIT();
    issue_chunk(1, sb + SM_STAGE + 1 * STAGE_BYTES, sIdx, n0, tid);
    CP_COMMIT();

    // Per-lane ldmatrix address invariants
    const int rA        = warp_m * 64 + (lane & 15);      // am adds +16 rows (row&7 invariant)
    const uint32_t aRow = (uint32_t)rA * 128u;
    const uint32_t aPh  = (uint32_t)((rA & 7) << 4);
    const int colAh     = (lane >> 4) * 16;
    const int rBb       = warp_n * 32 + (lane & 7) + ((lane >> 4) << 3);  // nb adds +16 rows
    const uint32_t bPh  = (uint32_t)((lane & 7) << 4);
    const int colBh     = ((lane >> 3) & 1) * 16;

    for (int c = 0; c < 64; c++) {
        CP_WAIT1();
        __syncthreads();

        if (c + 2 < 64)
            issue_chunk(c + 2, sb + SM_STAGE + ((c + 2) % 3) * STAGE_BYTES, sIdx, n0, tid);
        CP_COMMIT();

        const uint32_t Ab = sb + SM_STAGE + (c % 3) * STAGE_BYTES;
        const uint32_t Bb = Ab + A_BYTES;

#pragma unroll
        for (int ks = 0; ks < 4; ks++) {
            uint32_t a[4][4];
            const uint32_t offA = (uint32_t)(ks * 32 + colAh) ^ aPh;
#pragma unroll
            for (int am = 0; am < 4; am++)
                ldmx4(a[am][0], a[am][1], a[am][2], a[am][3],
                      Ab + aRow + (uint32_t)am * 2048u + offA);

            const uint32_t offB = (uint32_t)(ks * 32 + colBh) ^ bPh;
            uint32_t b[2][4];
#pragma unroll
            for (int nb = 0; nb < 2; nb++) {
                const int rB = rBb + nb * 16;
                ldmx4(b[nb][0], b[nb][1], b[nb][2], b[nb][3],
                      Bb + (uint32_t)rB * 128u + offB);
            }
#pragma unroll
            for (int am = 0; am < 4; am++) {
#pragma unroll
                for (int nb = 0; nb < 2; nb++) {
                    mma16816(acc[am][nb * 2 + 0], a[am], b[nb][0], b[nb][1]);
                    mma16816(acc[am][nb * 2 + 1], a[am], b[nb][2], b[nb][3]);
                }
            }
        }
    }

    // ---- Epilogue: bias add + store (row m -> b = m&3, l = m>>2) ----
    const bool tail = (tile == MTILES - 1);
#pragma unroll
    for (int am = 0; am < 4; am++) {
#pragma unroll
        for (int nn = 0; nn < 4; nn++) {
            const int o = n0 + warp_n * 32 + nn * 8 + (lane & 3) * 2;
            const float2 bz = *(const float2*)&bias[o];
            const int m = tile * 128 + warp_m * 64 + am * 16 + (lane >> 2);
            if (!tail || m < MTOT) {
                float2 v;
                v.x = acc[am][nn][0] + bz.x;
                v.y = acc[am][nn][1] + bz.y;
                *(float2*)&out[((size_t)(m & 3) * LL + (m >> 2)) * OO + o] = v;
            }
            const int m2 = m + 8;
            if (!tail || m2 < MTOT) {
                float2 v;
                v.x = acc[am][nn][2] + bz.x;
                v.y = acc[am][nn][3] + bz.y;
                *(float2*)&out[((size_t)(m2 & 3) * LL + (m2 >> 2)) * OO + o] = v;
            }
        }
    }
}

// ---------------- launch ----------------
extern "C" void kernel_launch(void* const* d_in, const int* in_sizes, int n_in,
                              void* d_out, int out_size) {
    const float* x    = (const float*)d_in[0];   // (4, 10000, 256) fp32
    const int*   idx  = (const int*)d_in[1];     // (10000, 16) int32
    const float* mask = (const float*)d_in[2];   // (16, 256, 256) fp32
    const float* bias = (const float*)d_in[3];   // (256,) fp32
    float*       out  = (float*)d_out;           // (4, 10000, 256) fp32

    (void)in_sizes; (void)n_in; (void)out_size;

    static bool attr_set = false;
    if (!attr_set) {
        cudaFuncSetAttribute(piconv_mma_kernel,
                             cudaFuncAttributeMaxDynamicSharedMemorySize, DYN_SMEM);
        attr_set = true;
    }

    prologue_kernel<<<3524, 1024>>>(x, mask);
    piconv_mma_kernel<<<dim3(MTILES, 4), NTHREADS, DYN_SMEM>>>(idx, bias, out);
}